// round 5
// baseline (speedup 1.0000x reference)
#include <cuda_runtime.h>

#define NT 5
#define A_FIX 128
#define MAX_PAD 160         // 128 atoms + up to 5*3 padding, rounded up
#define TPP 4               // threads per point
#define PTS_PER_BLK 64      // 256 threads / TPP

__device__ __forceinline__ float fast_sqrt(float x) {
    float r; asm("sqrt.approx.f32 %0, %1;" : "=f"(r) : "f"(x)); return r;
}
__device__ __forceinline__ float fast_ex2(float x) {
    float r; asm("ex2.approx.f32 %0, %1;" : "=f"(r) : "f"(x)); return r;
}
__device__ __forceinline__ float fast_rcp(float x) {
    float r; asm("rcp.approx.f32 %0, %1;" : "=f"(r) : "f"(x)); return r;
}
__device__ __forceinline__ float fast_rsq(float x) {
    float r; asm("rsqrt.approx.f32 %0, %1;" : "=f"(r) : "f"(x)); return r;
}

__global__ __launch_bounds__(256) void gnf_kernel(
    const float* __restrict__ coords,    // [B, A, 3]
    const int*   __restrict__ atom_types,// [B, A]
    const float* __restrict__ query,     // [B, P, 3]
    float*       __restrict__ out,       // [B, P, NT, 3]
    int P)
{
    // sc[a] = (L*x, L*y, L*z, |L*c|^2), bucket-sorted by type, padded to mult of 4
    __shared__ float4 sc[MAX_PAD];
    __shared__ int cnt[NT];
    __shared__ int offp[NT + 1];   // padded offsets

    const int b   = blockIdx.y;
    const int tid = threadIdx.x;
    const float L = 1.4426950408889634f;   // log2(e)

    // ---- bucket atoms by type ----
    if (tid < NT) cnt[tid] = 0;
    __syncthreads();

    int myT = -1, myR = 0;
    if (tid < A_FIX) {
        int t = atom_types[b * A_FIX + tid];
        if (t >= 0 && t < NT) { myT = t; myR = atomicAdd(&cnt[t], 1); }
    }
    __syncthreads();
    if (tid == 0) {
        int s = 0;
        #pragma unroll
        for (int t = 0; t < NT; t++) {
            offp[t] = s;
            s += (cnt[t] + 3) & ~3;      // pad each bucket to multiple of 4
        }
        offp[NT] = s;
    }
    __syncthreads();

    // fill all slots with sentinel (d2 huge -> e == 0 exactly)
    if (tid < MAX_PAD) sc[tid] = make_float4(0.0f, 0.0f, 0.0f, 1e30f);
    __syncthreads();

    if (myT >= 0) {
        const float* c = coords + (b * A_FIX + tid) * 3;
        float x = c[0] * L, y = c[1] * L, z = c[2] * L;
        sc[offp[myT] + myR] = make_float4(x, y, z, fmaf(x, x, fmaf(y, y, z * z)));
    }
    __syncthreads();

    // ---- main loop: TPP threads per point, atoms strided by TPP ----
    const int h = tid & (TPP - 1);
    const int p_raw = blockIdx.x * PTS_PER_BLK + (tid >> 2);
    const bool valid = (p_raw < P);
    const int p = valid ? p_raw : (P - 1);

    const float* q = query + ((long)b * P + p) * 3;
    const float qx = q[0] * L, qy = q[1] * L, qz = q[2] * L;
    const float q2x = 2.0f * qx, q2y = 2.0f * qy, q2z = 2.0f * qz;
    const float nqq = -fmaf(qx, qx, fmaf(qy, qy, qz * qz));   // -|qL|^2

    float* o = out + ((long)b * P + p) * (NT * 3);
    const float INVL = 0.6931471805599453f;  // ln(2)

    #pragma unroll
    for (int t = 0; t < NT; t++) {
        const int beg = offp[t];
        const int end = offp[t + 1];         // padded end: identical trips all lanes
        float sw = 0.0f, sxc = 0.0f, syc = 0.0f, szc = 0.0f;

        #pragma unroll 2
        for (int a = beg + h; a < end; a += TPP) {
            float4 c = sc[a];
            // 2c.q - |q|^2  (all pre-scaled by L)
            float dot2 = fmaf(c.x, q2x, fmaf(c.y, q2y, fmaf(c.z, q2z, nqq)));
            float d2 = c.w - dot2;           // = |c-q|^2 (may be -eps from rounding)
            float e = fast_ex2(-fast_sqrt(fabsf(d2)));   // exp(-true_dist)
            sw  += e;
            sxc = fmaf(e, c.x, sxc);
            syc = fmaf(e, c.y, syc);
            szc = fmaf(e, c.z, szc);
        }

        // reduce across the 4-lane group
        #pragma unroll
        for (int m = 1; m < TPP; m <<= 1) {
            sw  += __shfl_xor_sync(0xFFFFFFFFu, sw,  m);
            sxc += __shfl_xor_sync(0xFFFFFFFFu, sxc, m);
            syc += __shfl_xor_sync(0xFFFFFFFFu, syc, m);
            szc += __shfl_xor_sync(0xFFFFFFFFu, szc, m);
        }

        // lane (t & 3) of each quad stores this type
        if (valid && (t & (TPP - 1)) == h) {
            float gx = 0.0f, gy = 0.0f, gz = 0.0f;
            if (cnt[t] > 0) {
                float inv = fast_rcp(sw) * INVL;          // un-scale by L
                gx = (sxc - qx * sw) * inv;               // sum e*(cx-qx) / sum e
                gy = (syc - qy * sw) * inv;
                gz = (szc - qz * sw) * inv;
                float g2 = fmaf(gx, gx, fmaf(gy, gy, gz * gz));
                float f = fminf(1.0f, 0.3f * fast_rsq(fmaxf(g2, 1e-24f)));
                gx *= f; gy *= f; gz *= f;
            }
            o[t * 3 + 0] = gx;
            o[t * 3 + 1] = gy;
            o[t * 3 + 2] = gz;
        }
    }
}

extern "C" void kernel_launch(void* const* d_in, const int* in_sizes, int n_in,
                              void* d_out, int out_size)
{
    const float* coords     = (const float*)d_in[0];  // B*A*3
    const int*   atom_types = (const int*)  d_in[1];  // B*A
    const float* query      = (const float*)d_in[2];  // B*P*3

    const int A = A_FIX;
    const int B = in_sizes[1] / A;
    const int P = in_sizes[2] / (3 * B);

    dim3 grid((P + PTS_PER_BLK - 1) / PTS_PER_BLK, B);
    gnf_kernel<<<grid, 256>>>(coords, atom_types, query, (float*)d_out, P);
}

// round 6
// speedup vs baseline: 1.1425x; 1.1425x over previous
#include <cuda_runtime.h>

#define NT 5
#define A_FIX 128
#define MAX_PAD 144   // 128 atoms + up to 3 pad per bucket (5 buckets), rounded up

__device__ __forceinline__ float fast_sqrt(float x) {
    float r; asm("sqrt.approx.f32 %0, %1;" : "=f"(r) : "f"(x)); return r;
}
__device__ __forceinline__ float fast_ex2(float x) {
    float r; asm("ex2.approx.f32 %0, %1;" : "=f"(r) : "f"(x)); return r;
}
__device__ __forceinline__ float fast_rcp(float x) {
    float r; asm("rcp.approx.f32 %0, %1;" : "=f"(r) : "f"(x)); return r;
}
__device__ __forceinline__ float fast_rsq(float x) {
    float r; asm("rsqrt.approx.f32 %0, %1;" : "=f"(r) : "f"(x)); return r;
}

// one (point,atom) pair body, dot-product form; accumulates into one bank
#define PAIR(c, SW, SX, SY, SZ)                                               \
    {                                                                         \
        float dot2 = fmaf((c).x, q2x, fmaf((c).y, q2y, fmaf((c).z, q2z, nqq)));\
        float d2   = (c).w - dot2;            /* |c-q|^2, may be -eps */      \
        float e    = fast_ex2(-fast_sqrt(fabsf(d2)));                         \
        SW += e;                                                              \
        SX = fmaf(e, (c).x, SX);                                              \
        SY = fmaf(e, (c).y, SY);                                              \
        SZ = fmaf(e, (c).z, SZ);                                              \
    }

__global__ __launch_bounds__(256, 1) void gnf_kernel(
    const float* __restrict__ coords,    // [B, A, 3]
    const int*   __restrict__ atom_types,// [B, A]
    const float* __restrict__ query,     // [B, P, 3]
    float*       __restrict__ out,       // [B, P, NT, 3]
    int P)
{
    // sc[a] = (L*x, L*y, L*z, |L*c|^2), bucket-sorted by type, padded to mult of 4
    __shared__ float4 sc[MAX_PAD];
    __shared__ int cnt[NT];
    __shared__ int offp[NT + 1];

    const int b   = blockIdx.y;
    const int tid = threadIdx.x;
    const float L = 1.4426950408889634f;   // log2(e)

    // ---- bucket atoms by type ----
    if (tid < NT) cnt[tid] = 0;
    __syncthreads();

    int myT = -1, myR = 0;
    if (tid < A_FIX) {
        int t = atom_types[b * A_FIX + tid];
        if (t >= 0 && t < NT) { myT = t; myR = atomicAdd(&cnt[t], 1); }
    }
    __syncthreads();
    if (tid == 0) {
        int s = 0;
        #pragma unroll
        for (int t = 0; t < NT; t++) {
            offp[t] = s;
            s += (cnt[t] + 3) & ~3;        // pad each bucket to multiple of 4
        }
        offp[NT] = s;
    }
    __syncthreads();

    // sentinel fill: d2 huge -> e == 0 exactly
    if (tid < MAX_PAD) sc[tid] = make_float4(0.0f, 0.0f, 0.0f, 1e30f);
    __syncthreads();

    if (myT >= 0) {
        const float* c = coords + (b * A_FIX + tid) * 3;
        float x = c[0] * L, y = c[1] * L, z = c[2] * L;
        sc[offp[myT] + myR] = make_float4(x, y, z, fmaf(x, x, fmaf(y, y, z * z)));
    }
    __syncthreads();

    // ---- main: one point per thread, warp-uniform atom loop ----
    const int p = blockIdx.x * blockDim.x + tid;
    if (p >= P) return;

    const float* q = query + ((long)b * P + p) * 3;
    const float qx = q[0] * L, qy = q[1] * L, qz = q[2] * L;
    const float q2x = 2.0f * qx, q2y = 2.0f * qy, q2z = 2.0f * qz;
    const float nqq = -fmaf(qx, qx, fmaf(qy, qy, qz * qz));   // -|qL|^2

    float* o = out + ((long)b * P + p) * (NT * 3);
    const float INVL = 0.6931471805599453f;  // ln(2)

    #pragma unroll
    for (int t = 0; t < NT; t++) {
        const int beg = offp[t];
        const int end = offp[t + 1];        // (end-beg) % 4 == 0

        // 4 independent accumulator banks to break the serial chain
        float w0 = 0.f, x0 = 0.f, y0 = 0.f, z0 = 0.f;
        float w1 = 0.f, x1 = 0.f, y1 = 0.f, z1 = 0.f;
        float w2 = 0.f, x2 = 0.f, y2 = 0.f, z2 = 0.f;
        float w3 = 0.f, x3 = 0.f, y3 = 0.f, z3 = 0.f;

        for (int a = beg; a < end; a += 4) {
            float4 c0 = sc[a + 0];
            float4 c1 = sc[a + 1];
            float4 c2 = sc[a + 2];
            float4 c3 = sc[a + 3];
            PAIR(c0, w0, x0, y0, z0);
            PAIR(c1, w1, x1, y1, z1);
            PAIR(c2, w2, x2, y2, z2);
            PAIR(c3, w3, x3, y3, z3);
        }

        float sw  = (w0 + w1) + (w2 + w3);
        float sxc = (x0 + x1) + (x2 + x3);
        float syc = (y0 + y1) + (y2 + y3);
        float szc = (z0 + z1) + (z2 + z3);

        float gx = 0.0f, gy = 0.0f, gz = 0.0f;
        if (cnt[t] > 0) {
            float inv = fast_rcp(sw) * INVL;          // un-scale by L
            gx = (sxc - qx * sw) * inv;               // sum e*(cx-qx) / sum e
            gy = (syc - qy * sw) * inv;
            gz = (szc - qz * sw) * inv;
            float g2 = fmaf(gx, gx, fmaf(gy, gy, gz * gz));
            float f = fminf(1.0f, 0.3f * fast_rsq(fmaxf(g2, 1e-24f)));
            gx *= f; gy *= f; gz *= f;
        }
        o[t * 3 + 0] = gx;
        o[t * 3 + 1] = gy;
        o[t * 3 + 2] = gz;
    }
}

extern "C" void kernel_launch(void* const* d_in, const int* in_sizes, int n_in,
                              void* d_out, int out_size)
{
    const float* coords     = (const float*)d_in[0];  // B*A*3
    const int*   atom_types = (const int*)  d_in[1];  // B*A
    const float* query      = (const float*)d_in[2];  // B*P*3

    const int A = A_FIX;
    const int B = in_sizes[1] / A;
    const int P = in_sizes[2] / (3 * B);

    dim3 grid((P + 255) / 256, B);
    gnf_kernel<<<grid, 256>>>(coords, atom_types, query, (float*)d_out, P);
}